// round 3
// baseline (speedup 1.0000x reference)
#include <cuda_runtime.h>
#include <cuda_bf16.h>

// SimplifiedMambaBlock: the reference SSM scan has no input-injection term
// (h0 = 0, h <- exp(dt*A) * h), so h == 0 for all timesteps, ssm_out == 0,
// y == 0, out_proj(0) == 0, and the result is exactly `x + residual == x`.
// Exact-optimal kernel = copy x -> d_out (33.5 MB fp32).
//
// R3: SM copy is at the SM-path HBM roofline (~6.4 TB/s effective, 10.4 us).
// Probe the copy-engine path instead: cudaMemcpyAsync D2D captures as a
// graph memcpy node (allowed per harness rules), eliminates SM launch/tail
// overhead, and CE linear bursts typically sustain closer to raw HBM peak.

extern "C" void kernel_launch(void* const* d_in, const int* in_sizes, int n_in,
                              void* d_out, int out_size)
{
    const float* x = (const float*)d_in[0];   // (B, L, dim) fp32
    size_t bytes = (size_t)out_size * sizeof(float);  // 33.5 MB

    cudaMemcpyAsync(d_out, x, bytes, cudaMemcpyDeviceToDevice, 0);
}